// round 4
// baseline (speedup 1.0000x reference)
#include <cuda_runtime.h>

#define HW   4096
#define NC   128
#define CR   32
#define KK   49

// scratch for generated per-pixel kernels: [B=4][49][64*64]
__device__ float g_kernel[4 * KK * HW];

// ---------------------------------------------------------------------------
// Kernel 1: generate involution kernels.
// 256 blocks x 256 threads. Block = 64 pixels, 4 "parts" per pixel.
// ---------------------------------------------------------------------------
__global__ __launch_bounds__(256, 3) void gen_kernel(
    const float* __restrict__ x,  const float* __restrict__ w1,
    const float* __restrict__ b1, const float* __restrict__ gamma,
    const float* __restrict__ beta, const float* __restrict__ mean,
    const float* __restrict__ var,  const float* __restrict__ w2,
    const float* __restrict__ b2)
{
    __shared__ __align__(16) float w1t[NC * CR];      // [c][o]  16 KB
    __shared__ __align__(16) float w2tt[52 * CR];     // [t][o]  6.5 KB
    __shared__ __align__(16) float fbuf[4 * CR * 64]; // [part][o][pix] 32 KB
    __shared__ float s_scale[CR], s_shift[CR];

    const int tid = threadIdx.x;

    for (int i = tid; i < NC * CR; i += 256) {
        int o = i >> 7, c = i & 127;
        w1t[c * CR + o] = w1[i];
    }
    for (int i = tid; i < 52 * CR; i += 256)
        w2tt[i] = (i < KK * CR) ? w2[i] : 0.f;
    if (tid < CR) {
        float sc = gamma[tid] * rsqrtf(var[tid] + 1e-5f);
        s_scale[tid] = sc;
        s_shift[tid] = fmaf(b1[tid], sc, beta[tid] - mean[tid] * sc);
    }
    __syncthreads();

    const int pix_l = tid & 63;
    const int part  = tid >> 6;            // warp-uniform
    const int pixel = blockIdx.x * 64 + pix_l;
    const int b     = pixel >> 12;
    const int hw    = pixel & (HW - 1);

    // ---- stage 1: partial 1x1 conv over this part's 32 channels ----
    float fp[CR];
    #pragma unroll
    for (int o = 0; o < CR; o++) fp[o] = 0.f;

    const float* xp = x + ((size_t)(b * NC + part * 32)) * HW + hw;
    #pragma unroll 4
    for (int c = 0; c < 32; c++) {
        float xv = xp[(size_t)c * HW];
        const float4* wr = (const float4*)&w1t[(part * 32 + c) * CR];
        #pragma unroll
        for (int o4 = 0; o4 < 8; o4++) {
            float4 w = wr[o4];
            fp[o4*4+0] = fmaf(w.x, xv, fp[o4*4+0]);
            fp[o4*4+1] = fmaf(w.y, xv, fp[o4*4+1]);
            fp[o4*4+2] = fmaf(w.z, xv, fp[o4*4+2]);
            fp[o4*4+3] = fmaf(w.w, xv, fp[o4*4+3]);
        }
    }
    {
        float* fb = fbuf + part * (CR * 64) + pix_l;
        #pragma unroll
        for (int o = 0; o < CR; o++) fb[o * 64] = fp[o];
    }
    __syncthreads();

    // ---- stage 2: combine partials + BN + ReLU ----
    float f[CR];
    #pragma unroll
    for (int o = 0; o < CR; o++) {
        float v = fbuf[0*(CR*64) + o*64 + pix_l]
                + fbuf[1*(CR*64) + o*64 + pix_l]
                + fbuf[2*(CR*64) + o*64 + pix_l]
                + fbuf[3*(CR*64) + o*64 + pix_l];
        v = fmaf(v, s_scale[o], s_shift[o]);
        f[o] = fmaxf(v, 0.f);
    }

    // ---- stage 3: this part's 13 kernel outputs ----
    const int t0 = part * 13;
    float* kp = g_kernel + (size_t)b * KK * HW + hw;
    #pragma unroll
    for (int tt = 0; tt < 13; tt++) {
        int t = t0 + tt;
        const float4* wr = (const float4*)&w2tt[t * CR];
        float a0 = 0.f, a1 = 0.f, a2 = 0.f, a3 = 0.f;
        #pragma unroll
        for (int o4 = 0; o4 < 8; o4++) {
            float4 w = wr[o4];
            a0 = fmaf(w.x, f[o4*4+0], a0);
            a1 = fmaf(w.y, f[o4*4+1], a1);
            a2 = fmaf(w.z, f[o4*4+2], a2);
            a3 = fmaf(w.w, f[o4*4+3], a3);
        }
        if (t < KK)
            kp[(size_t)t * HW] = (a0 + a1) + (a2 + a3) + b2[t];
    }
}

// ---------------------------------------------------------------------------
// Kernel 2: involution accumulation, taps-outer / channels-inner.
// grid 1024 = (b, 16 4-row tiles, 16 8-channel groups), 128 threads.
// warp = one 64-wide output row, thread = 2 adjacent pixels x 8 channels.
// Per kernel-row i: 14 kv weights in regs (prefetched one row ahead),
// 16 independent accumulator chains -> high ILP at ~65 regs.
// ---------------------------------------------------------------------------
__global__ __launch_bounds__(128, 6) void inv_kernel(
    const float* __restrict__ x, float* __restrict__ out)
{
    __shared__ __align__(16) float xs[8 * 10 * 72];   // 23040 B

    const int bx = blockIdx.x;              // 0..1023
    const int b  = bx >> 8;
    const int ht = (bx >> 4) & 15;          // 16 row-tiles of 4
    const int cg = bx & 15;                 // 16 groups of 8 channels
    const int h0 = ht * 4;
    const int c0 = cg * 8;

    const int tid  = threadIdx.x;
    const int hloc = tid >> 5;              // 0..3
    const int lane = tid & 31;
    const int wloc = lane * 2;

    // ---- halo load: 4 warps x 2 channels each, division-free ----
    {
        #pragma unroll
        for (int ch = 0; ch < 2; ch++) {
            const int cc = hloc * 2 + ch;
            const float* xg = x + ((size_t)(b * NC + c0 + cc) << 12);
            float* xsc = xs + cc * (10 * 72);
            #pragma unroll
            for (int r = 0; r < 10; r++) {
                const int gr = h0 - 3 + r;
                const bool rok = (unsigned)gr < 64u;
                const float* xrow = xg + (gr << 6);
                #pragma unroll
                for (int s = 0; s < 3; s++) {
                    int col = lane + s * 32;
                    if (s < 2 || col < 72) {
                        int gc = col - 3;
                        float v = (rok && (unsigned)gc < 64u) ? xrow[gc] : 0.f;
                        xsc[r * 72 + col] = v;
                    }
                }
            }
        }
    }

    const float* kpix = g_kernel + (size_t)b * KK * HW + (h0 + hloc) * 64 + wloc;

    float ax[8], ay[8];
    #pragma unroll
    for (int cc = 0; cc < 8; cc++) { ax[cc] = 0.f; ay[cc] = 0.f; }

    // prefetch kernel row 0
    float2 kr[7], krn[7];
    #pragma unroll
    for (int j = 0; j < 7; j++)
        kr[j] = *(const float2*)(kpix + (size_t)j * HW);

    __syncthreads();

    #pragma unroll 1
    for (int i = 0; i < 7; i++) {
        // prefetch next kernel row while computing this one
        if (i < 6) {
            #pragma unroll
            for (int j = 0; j < 7; j++)
                krn[j] = *(const float2*)(kpix + (size_t)((i + 1) * 7 + j) * HW);
        }
        const float* xrow = xs + (hloc + i) * 72 + wloc;
        #pragma unroll
        for (int cc = 0; cc < 8; cc++) {
            const float2* rp = (const float2*)(xrow + cc * (10 * 72));
            float2 v0 = rp[0], v1 = rp[1], v2 = rp[2], v3 = rp[3];
            float a = ax[cc], y = ay[cc];
            a = fmaf(kr[0].x, v0.x, a);  y = fmaf(kr[0].y, v0.y, y);
            a = fmaf(kr[1].x, v0.y, a);  y = fmaf(kr[1].y, v1.x, y);
            a = fmaf(kr[2].x, v1.x, a);  y = fmaf(kr[2].y, v1.y, y);
            a = fmaf(kr[3].x, v1.y, a);  y = fmaf(kr[3].y, v2.x, y);
            a = fmaf(kr[4].x, v2.x, a);  y = fmaf(kr[4].y, v2.y, y);
            a = fmaf(kr[5].x, v2.y, a);  y = fmaf(kr[5].y, v3.x, y);
            a = fmaf(kr[6].x, v3.x, a);  y = fmaf(kr[6].y, v3.y, y);
            ax[cc] = a; ay[cc] = y;
        }
        #pragma unroll
        for (int j = 0; j < 7; j++) kr[j] = krn[j];
    }

    const size_t out_pix = (size_t)(h0 + hloc) * 64 + wloc;
    #pragma unroll
    for (int cc = 0; cc < 8; cc++) {
        float2 res; res.x = ax[cc]; res.y = ay[cc];
        *(float2*)(out + ((size_t)(b * NC + c0 + cc) << 12) + out_pix) = res;
    }
}

extern "C" void kernel_launch(void* const* d_in, const int* in_sizes, int n_in,
                              void* d_out, int out_size)
{
    const float* x     = (const float*)d_in[0];
    const float* w1    = (const float*)d_in[1];
    const float* b1    = (const float*)d_in[2];
    const float* gamma = (const float*)d_in[3];
    const float* beta  = (const float*)d_in[4];
    const float* mean  = (const float*)d_in[5];
    const float* var   = (const float*)d_in[6];
    const float* w2    = (const float*)d_in[7];
    const float* b2    = (const float*)d_in[8];

    gen_kernel<<<256, 256>>>(x, w1, b1, gamma, beta, mean, var, w2, b2);
    inv_kernel<<<1024, 128>>>(x, (float*)d_out);
}

// round 6
// speedup vs baseline: 1.2040x; 1.2040x over previous
#include <cuda_runtime.h>

#define HW   4096
#define NC   128
#define CR   32
#define KK   49

// scratch for generated per-pixel kernels: [B=4][49][64*64]
__device__ float g_kernel[4 * KK * HW];

// ---------------------------------------------------------------------------
// Kernel 1: generate involution kernels.
// 256 blocks x 256 threads. Block = 64 pixels, 4 "parts" per pixel.
// ---------------------------------------------------------------------------
__global__ __launch_bounds__(256, 3) void gen_kernel(
    const float* __restrict__ x,  const float* __restrict__ w1,
    const float* __restrict__ b1, const float* __restrict__ gamma,
    const float* __restrict__ beta, const float* __restrict__ mean,
    const float* __restrict__ var,  const float* __restrict__ w2,
    const float* __restrict__ b2)
{
    __shared__ __align__(16) float w1t[NC * CR];      // [c][o]  16 KB
    __shared__ __align__(16) float w2tt[52 * CR];     // [t][o]  6.5 KB
    __shared__ __align__(16) float fbuf[4 * CR * 64]; // [part][o][pix] 32 KB
    __shared__ float s_scale[CR], s_shift[CR];

    const int tid = threadIdx.x;

    for (int i = tid; i < NC * CR; i += 256) {
        int o = i >> 7, c = i & 127;
        w1t[c * CR + o] = w1[i];
    }
    for (int i = tid; i < 52 * CR; i += 256)
        w2tt[i] = (i < KK * CR) ? w2[i] : 0.f;
    if (tid < CR) {
        float sc = gamma[tid] * rsqrtf(var[tid] + 1e-5f);
        s_scale[tid] = sc;
        s_shift[tid] = fmaf(b1[tid], sc, beta[tid] - mean[tid] * sc);
    }
    __syncthreads();

    const int pix_l = tid & 63;
    const int part  = tid >> 6;            // warp-uniform
    const int pixel = blockIdx.x * 64 + pix_l;
    const int b     = pixel >> 12;
    const int hw    = pixel & (HW - 1);

    // ---- stage 1: partial 1x1 conv over this part's 32 channels ----
    float fp[CR];
    #pragma unroll
    for (int o = 0; o < CR; o++) fp[o] = 0.f;

    const float* xp = x + ((size_t)(b * NC + part * 32)) * HW + hw;
    #pragma unroll 8
    for (int c = 0; c < 32; c++) {
        float xv = xp[(size_t)c * HW];
        const float4* wr = (const float4*)&w1t[(part * 32 + c) * CR];
        #pragma unroll
        for (int o4 = 0; o4 < 8; o4++) {
            float4 w = wr[o4];
            fp[o4*4+0] = fmaf(w.x, xv, fp[o4*4+0]);
            fp[o4*4+1] = fmaf(w.y, xv, fp[o4*4+1]);
            fp[o4*4+2] = fmaf(w.z, xv, fp[o4*4+2]);
            fp[o4*4+3] = fmaf(w.w, xv, fp[o4*4+3]);
        }
    }
    {
        float* fb = fbuf + part * (CR * 64) + pix_l;
        #pragma unroll
        for (int o = 0; o < CR; o++) fb[o * 64] = fp[o];
    }
    __syncthreads();

    // ---- stage 2: combine partials + BN + ReLU ----
    float f[CR];
    #pragma unroll
    for (int o = 0; o < CR; o++) {
        float v = fbuf[0*(CR*64) + o*64 + pix_l]
                + fbuf[1*(CR*64) + o*64 + pix_l]
                + fbuf[2*(CR*64) + o*64 + pix_l]
                + fbuf[3*(CR*64) + o*64 + pix_l];
        v = fmaf(v, s_scale[o], s_shift[o]);
        f[o] = fmaxf(v, 0.f);
    }

    // ---- stage 3: this part's 13 kernel outputs ----
    const int t0 = part * 13;
    float* kp = g_kernel + (size_t)b * KK * HW + hw;
    #pragma unroll
    for (int tt = 0; tt < 13; tt++) {
        int t = t0 + tt;
        const float4* wr = (const float4*)&w2tt[t * CR];
        float a0 = 0.f, a1 = 0.f, a2 = 0.f, a3 = 0.f;
        #pragma unroll
        for (int o4 = 0; o4 < 8; o4++) {
            float4 w = wr[o4];
            a0 = fmaf(w.x, f[o4*4+0], a0);
            a1 = fmaf(w.y, f[o4*4+1], a1);
            a2 = fmaf(w.z, f[o4*4+2], a2);
            a3 = fmaf(w.w, f[o4*4+3], a3);
        }
        if (t < KK)
            kp[(size_t)t * HW] = (a0 + a1) + (a2 + a3) + b2[t];
    }
}

// ---------------------------------------------------------------------------
// Kernel 2: involution accumulation, taps-outer / channels-inner.
// grid 1024 = (b, 16 4-row tiles, 16 8-channel groups), 128 threads.
// Halo loaded with 10 aligned LDG.128 per thread (low MLP_p1 -> low CTA
// spread); edge/OOB columns zeroed in a tiny second pass.
// smem layout: xs[ch][10 rows][72 cols], smem col c <-> global col c-3.
// ---------------------------------------------------------------------------
__global__ __launch_bounds__(128, 6) void inv_kernel(
    const float* __restrict__ x, float* __restrict__ out)
{
    __shared__ __align__(16) float xs[8 * 10 * 72];   // 23040 B

    const int bx = blockIdx.x;              // 0..1023
    const int b  = bx >> 8;
    const int ht = (bx >> 4) & 15;          // 16 row-tiles of 4
    const int cg = bx & 15;                 // 16 groups of 8 channels
    const int h0 = ht * 4;
    const int c0 = cg * 8;

    const int tid  = threadIdx.x;
    const int hloc = tid >> 5;              // 0..3
    const int lane = tid & 31;
    const int wloc = lane * 2;

    // ---- halo main fill: 1280 aligned float4 loads (10 per thread) ----
    // (ch, r, k): gc = 4k (k=0..15), smem col = 3 + 4k
    #pragma unroll
    for (int it = 0; it < 10; it++) {
        int idx = tid + it * 128;           // 0..1279
        int ch  = idx / 160;
        int rem = idx - ch * 160;
        int r   = rem >> 4;
        int k   = rem & 15;
        int gr  = h0 - 3 + r;
        float4 v = make_float4(0.f, 0.f, 0.f, 0.f);
        if ((unsigned)gr < 64u)
            v = *(const float4*)(x + ((size_t)(b * NC + c0 + ch) << 12)
                                   + (gr << 6) + (k << 2));
        float* d = xs + ch * 720 + r * 72 + 3 + (k << 2);
        d[0] = v.x; d[1] = v.y; d[2] = v.z; d[3] = v.w;
    }
    // ---- halo edges: cols 0..2 (gc<0) and 67..71 (gc>63) -> zero ----
    #pragma unroll
    for (int it = 0; it < 5; it++) {
        int idx = tid + it * 128;           // 0..639
        int ch  = idx / 80;
        int rem = idx - ch * 80;
        int r   = rem >> 3;
        int e   = rem & 7;                  // 0..7
        int col = (e < 3) ? e : (64 + e);   // 0,1,2,67..71
        xs[ch * 720 + r * 72 + col] = 0.f;
    }

    const float* kpix = g_kernel + (size_t)b * KK * HW + (h0 + hloc) * 64 + wloc;

    float ax[8], ay[8];
    #pragma unroll
    for (int cc = 0; cc < 8; cc++) { ax[cc] = 0.f; ay[cc] = 0.f; }

    // prefetch kernel row 0
    float2 kr[7], krn[7];
    #pragma unroll
    for (int j = 0; j < 7; j++)
        kr[j] = *(const float2*)(kpix + (size_t)j * HW);

    __syncthreads();

    #pragma unroll 1
    for (int i = 0; i < 7; i++) {
        // prefetch next kernel row while computing this one
        if (i < 6) {
            #pragma unroll
            for (int j = 0; j < 7; j++)
                krn[j] = *(const float2*)(kpix + (size_t)((i + 1) * 7 + j) * HW);
        }
        const float* xrow = xs + (hloc + i) * 72 + wloc;
        #pragma unroll
        for (int cc = 0; cc < 8; cc++) {
            const float2* rp = (const float2*)(xrow + cc * 720);
            float2 v0 = rp[0], v1 = rp[1], v2 = rp[2], v3 = rp[3];
            float a = ax[cc], y = ay[cc];
            a = fmaf(kr[0].x, v0.x, a);  y = fmaf(kr[0].y, v0.y, y);
            a = fmaf(kr[1].x, v0.y, a);  y = fmaf(kr[1].y, v1.x, y);
            a = fmaf(kr[2].x, v1.x, a);  y = fmaf(kr[2].y, v1.y, y);
            a = fmaf(kr[3].x, v1.y, a);  y = fmaf(kr[3].y, v2.x, y);
            a = fmaf(kr[4].x, v2.x, a);  y = fmaf(kr[4].y, v2.y, y);
            a = fmaf(kr[5].x, v2.y, a);  y = fmaf(kr[5].y, v3.x, y);
            a = fmaf(kr[6].x, v3.x, a);  y = fmaf(kr[6].y, v3.y, y);
            ax[cc] = a; ay[cc] = y;
        }
        #pragma unroll
        for (int j = 0; j < 7; j++) kr[j] = krn[j];
    }

    const size_t out_pix = (size_t)(h0 + hloc) * 64 + wloc;
    #pragma unroll
    for (int cc = 0; cc < 8; cc++) {
        float2 res; res.x = ax[cc]; res.y = ay[cc];
        *(float2*)(out + ((size_t)(b * NC + c0 + cc) << 12) + out_pix) = res;
    }
}

extern "C" void kernel_launch(void* const* d_in, const int* in_sizes, int n_in,
                              void* d_out, int out_size)
{
    const float* x     = (const float*)d_in[0];
    const float* w1    = (const float*)d_in[1];
    const float* b1    = (const float*)d_in[2];
    const float* gamma = (const float*)d_in[3];
    const float* beta  = (const float*)d_in[4];
    const float* mean  = (const float*)d_in[5];
    const float* var   = (const float*)d_in[6];
    const float* w2    = (const float*)d_in[7];
    const float* b2    = (const float*)d_in[8];

    gen_kernel<<<256, 256>>>(x, w1, b1, gamma, beta, mean, var, w2, b2);
    inv_kernel<<<1024, 128>>>(x, (float*)d_out);
}